// round 8
// baseline (speedup 1.0000x reference)
#include <cuda_runtime.h>

#define GH 31
#define GW 51
#define PADC 30
#define KS 61
#define NBOX 20
#define BATCH 16
#define OH 1080
#define OW 1920
#define RPB 8                     // output rows per tile
#define NTILES (BATCH * (OH/RPB)) // 2160
#define NB 592                    // 4 blocks/SM * 148 SMs: one wave, guaranteed resident

// Scratch (no allocations allowed).
__device__ float g_xout[BATCH * OW];
__device__ float g_yout[BATCH * OH];
__device__ unsigned int g_arrive;   // monotonic grid-barrier ticket counter

// ---------------------------------------------------------------------------
// Separable KDE (proven in R5): exp(-0.5(dx^2/w+dy^2/h)) = Ex(wi)*Ey(hi).
// Writes g_xout[b][1920], g_yout[b][1080].
// ---------------------------------------------------------------------------
__device__ void sal_work(const float* __restrict__ bboxes, int b) {
    const int tid  = threadIdx.x;
    const int lane = tid & 31;
    const int w    = tid >> 5;

    __shared__ float exs[NBOX][GW];   // Ex_n[w] * SEy_n * inv_n
    __shared__ float eys[NBOX][GH];   // Ey_n[h] * SEx_n * inv_n
    __shared__ float xsal[GW], ysal[GH], filt[KS], xgrid[GW], ygrid[GH];

    // Gaussian filter (reference computes in float64 then casts).
    if (tid < KS) {
        double x = (double)tid - (double)PADC;
        filt[tid] = (float)exp(-4.0 * 0.693147180559945309 * x * x / (13.0 * 13.0));
    }

    // Warp w handles boxes n = w, w+8, w+16.
    for (int n = w; n < NBOX; n += 8) {
        const float* bb = bboxes + (b * NBOX + n) * 4;
        const float x1 = bb[0], y1 = bb[1], x2 = bb[2], y2 = bb[3];
        const float bw = x2 - x1, bh = y2 - y1;
        const float cx = x1 + 0.5f * bw, cy = y1 + 0.5f * bh;
        const float invw = 1.0f / bw, invh = 1.0f / bh;

        const float dx0 = cx - (float)lane * (1920.0f / 50.0f);
        const float dx1 = cx - (float)(lane + 32) * (1920.0f / 50.0f);
        const float dy0 = cy - (float)lane * (1080.0f / 30.0f);
        const float ex0 = expf(-0.5f * dx0 * dx0 * invw);
        const float ex1 = (lane < GW - 32) ? expf(-0.5f * dx1 * dx1 * invw) : 0.0f;
        const float ey0 = (lane < GH) ? expf(-0.5f * dy0 * dy0 * invh) : 0.0f;

        float sx = ex0 + ex1;
        float sy = ey0;
        #pragma unroll
        for (int s = 16; s > 0; s >>= 1) {
            sx += __shfl_xor_sync(0xffffffffu, sx, s);
            sy += __shfl_xor_sync(0xffffffffu, sy, s);
        }
        const float inv = 1.0f / (1e-5f + sx * sy);
        exs[n][lane] = ex0 * sy * inv;
        if (lane < GW - 32) exs[n][lane + 32] = ex1 * sy * inv;
        if (lane < GH)      eys[n][lane]      = ey0 * sx * inv;
    }
    __syncthreads();

    // Combine marginals (+ uniform bias summed over boxes and folded axis).
    const float bias = (float)NBOX * (1.0f / (float)(KS * KS));
    if (tid < GW) {
        float s = (float)GH * bias;
        #pragma unroll
        for (int n = 0; n < NBOX; n++) s += exs[n][tid];
        xsal[tid] = s;
    }
    if (tid >= 64 && tid < 64 + GH) {
        const int hh = tid - 64;
        float s = (float)GW * bias;
        #pragma unroll
        for (int n = 0; n < NBOX; n++) s += eys[n][hh];
        ysal[hh] = s;
    }
    __syncthreads();

    // 61-tap valid convs on reflect-padded marginals; grid = clip(o/w*2-1).
    if (tid < GW) {
        const int o = tid;
        float ws = 0.0f, os = 0.0f;
        #pragma unroll
        for (int k = 0; k < KS; k++) {
            const int j = o + k - PADC;
            const int idx = j < 0 ? -j : (j > GW - 1 ? 2 * (GW - 1) - j : j);
            const float v = xsal[idx];
            const float P = (float)(o + k - PADC) / (float)(GW - 1);
            const float f = filt[k];
            ws += v * f;
            os += P * v * f;
        }
        float g = os / ws * 2.0f - 1.0f;
        xgrid[o] = fminf(1.0f, fmaxf(-1.0f, g));
    }
    if (tid >= 64 && tid < 64 + GH) {
        const int o = tid - 64;
        float ws = 0.0f, os = 0.0f;
        #pragma unroll
        for (int k = 0; k < KS; k++) {
            const int j = o + k - PADC;
            const int idx = j < 0 ? -j : (j > GH - 1 ? 2 * (GH - 1) - j : j);
            const float v = ysal[idx];
            const float P = (float)(o + k - PADC) / (float)(GH - 1);
            const float f = filt[k];
            ws += v * f;
            os += P * v * f;
        }
        float g = os / ws * 2.0f - 1.0f;
        ygrid[o] = fminf(1.0f, fmaxf(-1.0f, g));
    }
    __syncthreads();

    // Align-corners 1D bilinear interp to the output axes.
    for (int ox = tid; ox < OW; ox += 256) {
        const float pos = (float)ox * ((float)(GW - 1) / (float)(OW - 1));
        int x0 = (int)floorf(pos);
        if (x0 > GW - 1) x0 = GW - 1;
        const float t = pos - (float)x0;
        const int x1 = min(x0 + 1, GW - 1);
        g_xout[b * OW + ox] = xgrid[x0] * (1.0f - t) + xgrid[x1] * t;
    }
    for (int oy = tid; oy < OH; oy += 256) {
        const float pos = (float)oy * ((float)(GH - 1) / (float)(OH - 1));
        int y0 = (int)floorf(pos);
        if (y0 > GH - 1) y0 = GH - 1;
        const float t = pos - (float)y0;
        const int y1 = min(y0 + 1, GH - 1);
        g_yout[b * OH + oy] = ygrid[y0] * (1.0f - t) + ygrid[y1] * t;
    }
}

// ---------------------------------------------------------------------------
// Single-wave persistent kernel: blocks 0..15 produce sal; grid barrier
// (monotonic ticket counter -> replay-safe, no reset); then all 592 blocks
// grid-stride the 2160 (batch, 8-row) tiles with streaming stores.
// ---------------------------------------------------------------------------
__global__ __launch_bounds__(256) void mono_kernel(const float* __restrict__ bboxes,
                                                   float4* __restrict__ out) {
    const int bid = blockIdx.x;
    const int tid = threadIdx.x;

    // Phase 1: producers.
    if (bid < BATCH) {
        sal_work(bboxes, bid);
        __syncthreads();
        __threadfence();
    }

    // Grid barrier. All NB blocks are resident (one wave by construction).
    __shared__ unsigned int s_go;
    if (tid == 0) {
        const unsigned int ticket = atomicAdd(&g_arrive, 1u);
        const unsigned int target = (ticket / NB + 1u) * NB;
        while (atomicAdd(&g_arrive, 0u) < target) __nanosleep(64);
        __threadfence();
        s_go = 1u;
    }
    __syncthreads();
    (void)s_go;

    // Phase 2: persistent fill. Tile g = (b, rtile).
    for (int g = bid; g < NTILES; g += NB) {
        const int b  = g / (OH / RPB);
        const int r0 = (g - b * (OH / RPB)) * RPB;

        const float2* xrow = reinterpret_cast<const float2*>(g_xout + b * OW);
        const float2 xv0 = xrow[tid];
        const float2 xv1 = xrow[tid + 256];
        const float2 xv2 = xrow[tid + 512];
        const bool   has3 = (tid < OW / 2 - 768);        // 960-768 = 192
        const float2 xv3 = has3 ? xrow[tid + 768] : make_float2(0.f, 0.f);

        float yv[RPB];
        #pragma unroll
        for (int r = 0; r < RPB; r++) yv[r] = g_yout[b * OH + r0 + r];

        float4* base = out + (size_t)(b * OH + r0) * (OW / 2);
        #pragma unroll
        for (int r = 0; r < RPB; r++) {
            float4* row = base + (size_t)r * (OW / 2);
            const float y = yv[r];
            __stcs(row + tid,       make_float4(xv0.x, y, xv0.y, y));
            __stcs(row + tid + 256, make_float4(xv1.x, y, xv1.y, y));
            __stcs(row + tid + 512, make_float4(xv2.x, y, xv2.y, y));
            if (has3)
                __stcs(row + tid + 768, make_float4(xv3.x, y, xv3.y, y));
        }
    }
}

extern "C" void kernel_launch(void* const* d_in, const int* in_sizes, int n_in,
                              void* d_out, int out_size) {
    // d_in[0] = imgs (unused: only its batch dim matters, fixed at 16)
    // d_in[1] = gt_bboxes [16, 20, 4] float32
    const float* bboxes = (const float*)d_in[1];

    mono_kernel<<<NB, 256>>>(bboxes, (float4*)d_out);
}

// round 9
// speedup vs baseline: 1.0117x; 1.0117x over previous
#include <cuda_runtime.h>

#define GH 31
#define GW 51
#define PADC 30
#define KS 61
#define NBOX 20
#define BATCH 16
#define OH 1080
#define OW 1920
#define RPB 8                     // output rows per tile
#define NTILES (BATCH * (OH/RPB)) // 2160
#define NB 592                    // 4 blocks/SM * 148 SMs: one wave, guaranteed resident

// Scratch (no allocations allowed).
__device__ float g_xout[BATCH * OW];
__device__ float g_yout[BATCH * OH];
__device__ volatile unsigned int g_arrive;   // monotonic barrier counter (never reset)

// ---------------------------------------------------------------------------
// Separable KDE (proven): exp(-0.5(dx^2/w+dy^2/h)) = Ex(wi)*Ey(hi).
// Writes g_xout[b][1920], g_yout[b][1080].
// ---------------------------------------------------------------------------
__device__ void sal_work(const float* __restrict__ bboxes, int b) {
    const int tid  = threadIdx.x;
    const int lane = tid & 31;
    const int w    = tid >> 5;

    __shared__ float exs[NBOX][GW];   // Ex_n[w] * SEy_n * inv_n
    __shared__ float eys[NBOX][GH];   // Ey_n[h] * SEx_n * inv_n
    __shared__ float xsal[GW], ysal[GH], filt[KS], xgrid[GW], ygrid[GH];

    // Gaussian filter (float is plenty: rel budget 1e-3, float exp ~1e-7).
    if (tid < KS) {
        const float x = (float)tid - (float)PADC;
        filt[tid] = expf(-4.0f * 0.6931471805599453f * x * x / (13.0f * 13.0f));
    }

    // Warp w handles boxes n = w, w+8, w+16.
    for (int n = w; n < NBOX; n += 8) {
        const float* bb = bboxes + (b * NBOX + n) * 4;
        const float x1 = bb[0], y1 = bb[1], x2 = bb[2], y2 = bb[3];
        const float bw = x2 - x1, bh = y2 - y1;
        const float cx = x1 + 0.5f * bw, cy = y1 + 0.5f * bh;
        const float invw = 1.0f / bw, invh = 1.0f / bh;

        const float dx0 = cx - (float)lane * (1920.0f / 50.0f);
        const float dx1 = cx - (float)(lane + 32) * (1920.0f / 50.0f);
        const float dy0 = cy - (float)lane * (1080.0f / 30.0f);
        const float ex0 = expf(-0.5f * dx0 * dx0 * invw);
        const float ex1 = (lane < GW - 32) ? expf(-0.5f * dx1 * dx1 * invw) : 0.0f;
        const float ey0 = (lane < GH) ? expf(-0.5f * dy0 * dy0 * invh) : 0.0f;

        float sx = ex0 + ex1;
        float sy = ey0;
        #pragma unroll
        for (int s = 16; s > 0; s >>= 1) {
            sx += __shfl_xor_sync(0xffffffffu, sx, s);
            sy += __shfl_xor_sync(0xffffffffu, sy, s);
        }
        const float inv = 1.0f / (1e-5f + sx * sy);
        exs[n][lane] = ex0 * sy * inv;
        if (lane < GW - 32) exs[n][lane + 32] = ex1 * sy * inv;
        if (lane < GH)      eys[n][lane]      = ey0 * sx * inv;
    }
    __syncthreads();

    // Combine marginals (+ uniform bias summed over boxes and folded axis).
    // Global S.sum() normalization cancels in ox/wx, oy/wy: skipped.
    const float bias = (float)NBOX * (1.0f / (float)(KS * KS));
    if (tid < GW) {
        float s = (float)GH * bias;
        #pragma unroll
        for (int n = 0; n < NBOX; n++) s += exs[n][tid];
        xsal[tid] = s;
    }
    if (tid >= 64 && tid < 64 + GH) {
        const int hh = tid - 64;
        float s = (float)GW * bias;
        #pragma unroll
        for (int n = 0; n < NBOX; n++) s += eys[n][hh];
        ysal[hh] = s;
    }
    __syncthreads();

    // 61-tap valid convs on reflect-padded marginals; grid = clip(o/w*2-1).
    if (tid < GW) {
        const int o = tid;
        float ws = 0.0f, os = 0.0f;
        #pragma unroll
        for (int k = 0; k < KS; k++) {
            const int j = o + k - PADC;
            const int idx = j < 0 ? -j : (j > GW - 1 ? 2 * (GW - 1) - j : j);
            const float v = xsal[idx];
            const float P = (float)(o + k - PADC) / (float)(GW - 1);
            const float f = filt[k];
            ws += v * f;
            os += P * v * f;
        }
        float g = os / ws * 2.0f - 1.0f;
        xgrid[o] = fminf(1.0f, fmaxf(-1.0f, g));
    }
    if (tid >= 64 && tid < 64 + GH) {
        const int o = tid - 64;
        float ws = 0.0f, os = 0.0f;
        #pragma unroll
        for (int k = 0; k < KS; k++) {
            const int j = o + k - PADC;
            const int idx = j < 0 ? -j : (j > GH - 1 ? 2 * (GH - 1) - j : j);
            const float v = ysal[idx];
            const float P = (float)(o + k - PADC) / (float)(GH - 1);
            const float f = filt[k];
            ws += v * f;
            os += P * v * f;
        }
        float g = os / ws * 2.0f - 1.0f;
        ygrid[o] = fminf(1.0f, fmaxf(-1.0f, g));
    }
    __syncthreads();

    // Align-corners 1D bilinear interp to the output axes.
    for (int ox = tid; ox < OW; ox += 256) {
        const float pos = (float)ox * ((float)(GW - 1) / (float)(OW - 1));
        int x0 = (int)floorf(pos);
        if (x0 > GW - 1) x0 = GW - 1;
        const float t = pos - (float)x0;
        const int x1 = min(x0 + 1, GW - 1);
        g_xout[b * OW + ox] = xgrid[x0] * (1.0f - t) + xgrid[x1] * t;
    }
    for (int oy = tid; oy < OH; oy += 256) {
        const float pos = (float)oy * ((float)(GH - 1) / (float)(OH - 1));
        int y0 = (int)floorf(pos);
        if (y0 > GH - 1) y0 = GH - 1;
        const float t = pos - (float)y0;
        const int y1 = min(y0 + 1, GH - 1);
        g_yout[b * OH + oy] = ygrid[y0] * (1.0f - t) + ygrid[y1] * t;
    }
}

// ---------------------------------------------------------------------------
// Single-wave persistent kernel. Blocks 0..15 produce sal; grid barrier with
// atomic ARRIVE + volatile-LOAD polling (no atomic storm); then all 592
// blocks grid-stride the 2160 (batch, 8-row) tiles with streaming stores.
// Barrier counter is monotonic -> replay-safe without resets.
// ---------------------------------------------------------------------------
__global__ void __launch_bounds__(256, 4)
mono_kernel(const float* __restrict__ bboxes, float4* __restrict__ out) {
    const int bid = blockIdx.x;
    const int tid = threadIdx.x;

    // Phase 1: producers.
    if (bid < BATCH) {
        sal_work(bboxes, bid);
        __threadfence();   // all producer threads: publish global writes
        __syncthreads();
    }

    // Grid barrier (all NB blocks resident: one wave by construction).
    __shared__ unsigned int s_target;
    if (tid == 0) {
        const unsigned int ticket = atomicAdd((unsigned int*)&g_arrive, 1u);
        s_target = (ticket / NB + 1u) * NB;
    }
    __syncthreads();
    const unsigned int target = s_target;
    if (tid == 0) {
        while (g_arrive < target) __nanosleep(128);   // volatile load poll
        __threadfence();                              // acquire
    }
    __syncthreads();

    // Phase 2: persistent fill. Tile g = (b, rtile).
    for (int g = bid; g < NTILES; g += NB) {
        const int b  = g / (OH / RPB);
        const int r0 = (g - b * (OH / RPB)) * RPB;

        const float2* xrow = reinterpret_cast<const float2*>(g_xout + b * OW);
        const float2 xv0 = xrow[tid];
        const float2 xv1 = xrow[tid + 256];
        const float2 xv2 = xrow[tid + 512];
        const bool   has3 = (tid < OW / 2 - 768);        // 960-768 = 192
        const float2 xv3 = has3 ? xrow[tid + 768] : make_float2(0.f, 0.f);

        float yv[RPB];
        #pragma unroll
        for (int r = 0; r < RPB; r++) yv[r] = g_yout[b * OH + r0 + r];

        float4* base = out + (size_t)(b * OH + r0) * (OW / 2);
        #pragma unroll
        for (int r = 0; r < RPB; r++) {
            float4* row = base + (size_t)r * (OW / 2);
            const float y = yv[r];
            __stcs(row + tid,       make_float4(xv0.x, y, xv0.y, y));
            __stcs(row + tid + 256, make_float4(xv1.x, y, xv1.y, y));
            __stcs(row + tid + 512, make_float4(xv2.x, y, xv2.y, y));
            if (has3)
                __stcs(row + tid + 768, make_float4(xv3.x, y, xv3.y, y));
        }
    }
}

extern "C" void kernel_launch(void* const* d_in, const int* in_sizes, int n_in,
                              void* d_out, int out_size) {
    // d_in[0] = imgs (unused: only its batch dim matters, fixed at 16)
    // d_in[1] = gt_bboxes [16, 20, 4] float32
    const float* bboxes = (const float*)d_in[1];

    mono_kernel<<<NB, 256>>>(bboxes, (float4*)d_out);
}